// round 14
// baseline (speedup 1.0000x reference)
#include <cuda_runtime.h>
#include <cuda_fp16.h>
#include <math.h>
#include <stdint.h>

#define T 2048
#define H 1024
#define M 512
#define E 32
#define TOPK 4
#define NROWS (T * TOPK)
#define PROWS (NROWS + 128)

// ------------------------- static device scratch ---------------------------
__device__ int      g_count[E];        // zero at load; re-zeroed by down_mma tail
__device__ int      g_done;
__device__ int      g_tok[E * T];
__device__ float    g_wt[E * T];
__device__ uint32_t g_hbufw[(size_t)PROWS * M / 2];   // half2 words
__device__ __half   g_xh[(size_t)T * H];
__device__ __half   g_wgh[(size_t)E * M * H];
__device__ __half   g_wuh[(size_t)E * M * H];
__device__ __half   g_wdh[(size_t)E * H * M];

// ------------------------- helpers -----------------------------------------
__device__ __forceinline__ uint32_t smem_u32(const void* p) {
    return (uint32_t)__cvta_generic_to_shared(p);
}
__device__ __forceinline__ uint32_t f2h2(float a, float b) {
    uint32_t r;
    asm("cvt.rn.f16x2.f32 %0, %1, %2;" : "=r"(r) : "f"(b), "f"(a));
    return r;
}
__device__ __forceinline__ uint4 pack4(float4 a, float4 b) {
    uint4 o;
    o.x = f2h2(a.x, a.y); o.y = f2h2(a.z, a.w);
    o.z = f2h2(b.x, b.y); o.w = f2h2(b.z, b.w);
    return o;
}
__device__ __forceinline__ void ldm4(uint32_t* r, uint32_t addr) {
    asm volatile("ldmatrix.sync.aligned.m8n8.x4.shared.b16 {%0,%1,%2,%3}, [%4];"
        : "=r"(r[0]), "=r"(r[1]), "=r"(r[2]), "=r"(r[3]) : "r"(addr));
}
__device__ __forceinline__ void mma_f16(float* c, const uint32_t* a, uint32_t b0, uint32_t b1) {
    asm volatile("mma.sync.aligned.m16n8k16.row.col.f32.f16.f16.f32 "
        "{%0,%1,%2,%3}, {%4,%5,%6,%7}, {%8,%9}, {%0,%1,%2,%3};"
        : "+f"(c[0]), "+f"(c[1]), "+f"(c[2]), "+f"(c[3])
        : "r"(a[0]), "r"(a[1]), "r"(a[2]), "r"(a[3]), "r"(b0), "r"(b1));
}
__device__ __forceinline__ void cp16(uint32_t dst, const void* src, int sz) {
    asm volatile("cp.async.cg.shared.global [%0], [%1], 16, %2;"
        :: "r"(dst), "l"(src), "r"(sz) : "memory");
}
#define CP_COMMIT() asm volatile("cp.async.commit_group;" ::: "memory")
#define CP_WAIT(n)  asm volatile("cp.async.wait_group %0;" :: "n"(n) : "memory")

#define RWORDS 20
#define RBYTES 80

// in-block scan of g_count -> soff (row base) and styp (ytile prefix)
#define BLOCK_SCAN(soff, styp)                                             \
    if (wid == 0) {                                                        \
        int c = g_count[lane];                                             \
        int ex = c;                                                        \
        _Pragma("unroll")                                                  \
        for (int o = 1; o < 32; o <<= 1) {                                 \
            int v = __shfl_up_sync(0xffffffffu, ex, o);                    \
            if (lane >= o) ex += v;                                        \
        }                                                                  \
        soff[lane] = ex - c;                                               \
        int ty = (c + 127) >> 7;                                           \
        int tp = ty;                                                       \
        _Pragma("unroll")                                                  \
        for (int o = 1; o < 32; o <<= 1) {                                 \
            int v = __shfl_up_sync(0xffffffffu, tp, o);                    \
            if (lane >= o) tp += v;                                        \
        }                                                                  \
        styp[lane] = tp - ty;                                              \
        if (lane == 31) styp[E] = tp;                                      \
    }                                                                      \
    __syncthreads();

// ------------------------- fused prep: router + wg/wu cvt + zero out --------
#define NW8  (E * M * H / 8)      // 2097152 uint4 per weight tensor
#define NZ4  (T * H / 4)          // 524288 output float4s
#define CVTN (2 * NW8 + NZ4)
#define CVTB ((CVTN + 255) / 256) // 18432
#define PREPB (T + CVTB)

__global__ void __launch_bounds__(256)
prep_kernel(const float* __restrict__ x, const float* __restrict__ gate_w,
            const float4* __restrict__ wg, const float4* __restrict__ wu,
            float* __restrict__ out) {
    if (blockIdx.x >= T) {
        // cvt / zero part
        int i = (blockIdx.x - T) * 256 + threadIdx.x;
        if (i >= CVTN) return;
        if (i < 2 * NW8) {
            const float4* src = (i < NW8) ? wg : wu;
            uint4* dst = (i < NW8) ? (uint4*)g_wgh : (uint4*)g_wuh;
            int k = (i < NW8) ? i : i - NW8;
            float4 a = src[2 * (size_t)k], b = src[2 * (size_t)k + 1];
            dst[k] = pack4(a, b);
        } else {
            ((float4*)out)[i - 2 * NW8] = make_float4(0.f, 0.f, 0.f, 0.f);
        }
        return;
    }
    // router part (one block per token, 256 threads)
    __shared__ float xs[H];
    __shared__ float logits[E];
    int t = blockIdx.x;
    const float* xr = x + (size_t)t * H;
    for (int i = threadIdx.x; i < H; i += 256) xs[i] = xr[i];
    __syncthreads();
    uint32_t* xh = (uint32_t*)(g_xh + (size_t)t * H);
    for (int i = threadIdx.x; i < H / 2; i += 256)
        xh[i] = f2h2(xs[2 * i], xs[2 * i + 1]);
    int warp = threadIdx.x >> 5, lane = threadIdx.x & 31;
    for (int e = warp; e < E; e += 8) {
        const float* w = gate_w + (size_t)e * H;
        float s = 0.f;
        for (int i = lane; i < H; i += 32) s += xs[i] * w[i];
        #pragma unroll
        for (int o = 16; o > 0; o >>= 1) s += __shfl_xor_sync(0xffffffffu, s, o);
        if (lane == 0) logits[e] = s;
    }
    __syncthreads();
    if (threadIdx.x == 0) {
        int ids[TOPK]; float vals[TOPK];
        unsigned used = 0;
        for (int k = 0; k < TOPK; k++) {
            float best = -INFINITY; int bi = 0;
            for (int e = 0; e < E; e++)
                if (!((used >> e) & 1u) && logits[e] > best) { best = logits[e]; bi = e; }
            used |= (1u << bi); ids[k] = bi; vals[k] = best;
        }
        float mx = vals[0], se = 0.f, w4[TOPK];
        for (int k = 0; k < TOPK; k++) { w4[k] = expf(vals[k] - mx); se += w4[k]; }
        float inv = 1.0f / se;
        for (int k = 0; k < TOPK; k++) {
            int e = ids[k];
            int pos = atomicAdd(&g_count[e], 1);
            g_tok[e * T + pos] = t * TOPK + k;
            g_wt[e * T + pos] = w4[k] * inv;
        }
    }
}

// ------------------------- gate/up fp16 mma GEMM ---------------------------
#define GU_STAGEW 5120
#define GU_STAGEB (GU_STAGEW * 4)
#define GU_SMEMB  (4 * GU_STAGEB)          // 81920 bytes

__global__ void __launch_bounds__(256, 2)
gateup_mma(const float4* __restrict__ wd) {
    extern __shared__ uint32_t sm[];
    __shared__ int   styp[E + 1];
    __shared__ int   soff[E];
    __shared__ int   said_s[128];
    __shared__ float swt_s[128];

    int tid = threadIdx.x, lane = tid & 31, wid = tid >> 5;
    int gid = lane >> 2, tig = lane & 3;
    int wm = wid & 3, wn = wid >> 2;

    // prologue: convert w_down to fp16 (striped across grid; down_mma launches later)
    for (int i = blockIdx.x * 256 + tid; i < NW8; i += gridDim.x * 256) {
        float4 a = wd[2 * (size_t)i], b = wd[2 * (size_t)i + 1];
        ((uint4*)g_wdh)[i] = pack4(a, b);
    }

    BLOCK_SCAN(soff, styp);
    int totalW = styp[E] * 8;

    uint32_t sbase = smem_u32(sm);
    int a_ro = lane & 15;
    int a_kw = (lane >> 4) * 16;
    uint32_t adrA0 = sbase + (uint32_t)(wm * 32 + a_ro) * RBYTES + a_kw;
    uint32_t adrA1 = adrA0 + 16 * RBYTES;
    int b_ro = (lane & 7) + ((lane & 16) >> 1);
    int b_kw = (lane & 8) ? 16 : 0;
    uint32_t adrG0 = sbase + 128 * RBYTES + (uint32_t)(wn * 32 + b_ro) * RBYTES + b_kw;
    uint32_t adrG1 = adrG0 + 16 * RBYTES;
    uint32_t adrU0 = adrG0 + 64 * RBYTES;
    uint32_t adrU1 = adrU0 + 16 * RBYTES;

    int ar = tid >> 1, aj = (tid & 1) * 2;
    int gr = tid >> 2, gj = tid & 3;

    for (int w = blockIdx.x; w < totalW; w += gridDim.x) {
        int ytl = w >> 3, xt = w & 7;
        int e = 0;
        while (styp[e + 1] <= ytl) e++;
        int t0 = (ytl - styp[e]) * 128;
        int m0 = xt * 64;
        int n  = g_count[e];
        int gbase = soff[e] + t0;

        __syncthreads();
        if (tid < 128) {
            int slot = t0 + tid;
            bool v = slot < n;
            said_s[tid] = v ? g_tok[e * T + slot] : -1;
            swt_s[tid]  = v ? g_wt[e * T + slot] : 0.f;
        }
        __syncthreads();

        int aid_a = said_s[ar];
        int apred = (aid_a >= 0) ? 16 : 0;
        const char* asrc0 = (const char*)(g_xh + (size_t)((aid_a < 0 ? 0 : aid_a) >> 2) * H) + aj * 16;
        const char* gsrc0 = (const char*)(g_wgh + ((size_t)e * M + m0 + gr) * H) + gj * 16;
        const char* usrc0 = (const char*)(g_wuh + ((size_t)e * M + m0 + gr) * H) + gj * 16;

        float accG[2][4][4], accU[2][4][4];
        #pragma unroll
        for (int i = 0; i < 2; i++)
            #pragma unroll
            for (int j = 0; j < 4; j++)
                #pragma unroll
                for (int q = 0; q < 4; q++) { accG[i][j][q] = 0.f; accU[i][j][q] = 0.f; }

        auto issue = [&](int c, int s) {
            uint32_t st = sbase + (uint32_t)s * GU_STAGEB;
            const char* as = asrc0 + c * 64;
            cp16(st + ar * RBYTES + aj * 16,      as,      apred);
            cp16(st + ar * RBYTES + aj * 16 + 16, as + 16, apred);
            cp16(st + 128 * RBYTES + gr * RBYTES + gj * 16, gsrc0 + c * 64, 16);
            cp16(st + 192 * RBYTES + gr * RBYTES + gj * 16, usrc0 + c * 64, 16);
        };
        auto compute = [&](int s) {
            uint32_t so = (uint32_t)s * GU_STAGEB;
            #pragma unroll
            for (int sub = 0; sub < 2; sub++) {
                uint32_t soo = so + sub * 32;
                uint32_t a0[4], a1[4], g0[4], g1[4], u0[4], u1[4];
                ldm4(a0, adrA0 + soo); ldm4(a1, adrA1 + soo);
                ldm4(g0, adrG0 + soo); ldm4(g1, adrG1 + soo);
                ldm4(u0, adrU0 + soo); ldm4(u1, adrU1 + soo);
                #pragma unroll
                for (int p = 0; p < 2; p++) {
                    const uint32_t* gg = p ? g1 : g0;
                    const uint32_t* uu = p ? u1 : u0;
                    #pragma unroll
                    for (int q = 0; q < 2; q++) {
                        int nt = p * 2 + q;
                        mma_f16(accG[0][nt], a0, gg[q * 2], gg[q * 2 + 1]);
                        mma_f16(accG[1][nt], a1, gg[q * 2], gg[q * 2 + 1]);
                        mma_f16(accU[0][nt], a0, uu[q * 2], uu[q * 2 + 1]);
                        mma_f16(accU[1][nt], a1, uu[q * 2], uu[q * 2 + 1]);
                    }
                }
            }
        };

        const int NC = H / 32;   // 32
        issue(0, 0); CP_COMMIT();
        issue(1, 1); CP_COMMIT();
        issue(2, 2); CP_COMMIT();
        CP_WAIT(2);
        __syncthreads();
        for (int c = 0; c < NC; c++) {
            compute(c & 3);
            if (c + 3 < NC) issue(c + 3, (c + 3) & 3);
            CP_COMMIT();
            CP_WAIT(2);
            __syncthreads();
        }

        #pragma unroll
        for (int mt = 0; mt < 2; mt++) {
            #pragma unroll
            for (int rh = 0; rh < 2; rh++) {
                int r = wm * 32 + mt * 16 + gid + rh * 8;
                int said = said_s[r];
                if (said < 0) continue;
                float wv = swt_s[r];
                uint32_t* hp = g_hbufw + (size_t)(gbase + r) * (M / 2)
                             + ((m0 + wn * 32) >> 1) + tig;
                #pragma unroll
                for (int nt = 0; nt < 4; nt++) {
                    float g0 = accG[mt][nt][rh * 2 + 0];
                    float g1 = accG[mt][nt][rh * 2 + 1];
                    float u0 = accU[mt][nt][rh * 2 + 0];
                    float u1 = accU[mt][nt][rh * 2 + 1];
                    float o0 = (g0 / (1.f + __expf(-g0))) * u0 * wv;
                    float o1 = (g1 / (1.f + __expf(-g1))) * u1 * wv;
                    hp[nt * 4] = f2h2(o0, o1);
                }
            }
        }
    }
}

// ------------------------- down fp16 mma GEMM ------------------------------
#define DN_STAGEW 5120
#define DN_STAGEB (DN_STAGEW * 4)
#define DN_SMEMB  (4 * DN_STAGEB)          // 81920 bytes

__global__ void __launch_bounds__(256, 2)
down_mma(float* __restrict__ out) {
    extern __shared__ uint32_t sm[];
    __shared__ int styp[E + 1];
    __shared__ int soff[E];
    __shared__ int said_s[128];

    int tid = threadIdx.x, lane = tid & 31, wid = tid >> 5;
    int gid = lane >> 2, tig = lane & 3;
    int wm = wid & 1, wn = wid >> 1;

    BLOCK_SCAN(soff, styp);
    int totalW = styp[E] * 8;

    uint32_t sbase = smem_u32(sm);
    int a_ro = lane & 15;
    int a_kw = (lane >> 4) * 16;
    uint32_t adrA[4];
    #pragma unroll
    for (int mt = 0; mt < 4; mt++)
        adrA[mt] = sbase + (uint32_t)(wm * 64 + mt * 16 + a_ro) * RBYTES + a_kw;
    int b_ro = (lane & 7) + ((lane & 16) >> 1);
    int b_kw = (lane & 8) ? 16 : 0;
    uint32_t adrW0 = sbase + 128 * RBYTES + (uint32_t)(wn * 32 + b_ro) * RBYTES + b_kw;
    uint32_t adrW1 = adrW0 + 16 * RBYTES;

    int ar = tid >> 1, aj = (tid & 1) * 2;

    for (int w = blockIdx.x; w < totalW; w += gridDim.x) {
        int ytl = w >> 3, xt = w & 7;
        int e = 0;
        while (styp[e + 1] <= ytl) e++;
        int t0 = (ytl - styp[e]) * 128;
        int h0 = xt * 128;
        int n  = g_count[e];
        int gbase = soff[e] + t0;

        __syncthreads();
        if (tid < 128) {
            int slot = t0 + tid;
            said_s[tid] = (slot < n) ? g_tok[e * T + slot] : -1;
        }
        __syncthreads();

        const char* asrc0 = (const char*)(g_hbufw + (size_t)(gbase + ar) * (M / 2)) + aj * 16;
        const char* wsrc0 = (const char*)(g_wdh + ((size_t)e * H + h0 + ar) * M) + aj * 16;

        float acc[4][4][4];
        #pragma unroll
        for (int i = 0; i < 4; i++)
            #pragma unroll
            for (int j = 0; j < 4; j++)
                #pragma unroll
                for (int q = 0; q < 4; q++) acc[i][j][q] = 0.f;

        auto issue = [&](int c, int s) {
            uint32_t st = sbase + (uint32_t)s * DN_STAGEB;
            const char* as = asrc0 + c * 64;
            const char* ws = wsrc0 + c * 64;
            cp16(st + ar * RBYTES + aj * 16,      as,      16);
            cp16(st + ar * RBYTES + aj * 16 + 16, as + 16, 16);
            cp16(st + 128 * RBYTES + ar * RBYTES + aj * 16,      ws,      16);
            cp16(st + 128 * RBYTES + ar * RBYTES + aj * 16 + 16, ws + 16, 16);
        };
        auto compute = [&](int s) {
            uint32_t so = (uint32_t)s * DN_STAGEB;
            #pragma unroll
            for (int sub = 0; sub < 2; sub++) {
                uint32_t soo = so + sub * 32;
                uint32_t a[4][4], w0[4], w1[4];
                #pragma unroll
                for (int mt = 0; mt < 4; mt++) ldm4(a[mt], adrA[mt] + soo);
                ldm4(w0, adrW0 + soo); ldm4(w1, adrW1 + soo);
                #pragma unroll
                for (int p = 0; p < 2; p++) {
                    const uint32_t* ww = p ? w1 : w0;
                    #pragma unroll
                    for (int q = 0; q < 2; q++) {
                        int nt = p * 2 + q;
                        #pragma unroll
                        for (int mt = 0; mt < 4; mt++)
                            mma_f16(acc[mt][nt], a[mt], ww[q * 2], ww[q * 2 + 1]);
                    }
                }
            }
        };

        const int NC = M / 32;   // 16
        issue(0, 0); CP_COMMIT();
        issue(1, 1); CP_COMMIT();
        issue(2, 2); CP_COMMIT();
        CP_WAIT(2);
        __syncthreads();
        for (int c = 0; c < NC; c++) {
            compute(c & 3);
            if (c + 3 < NC) issue(c + 3, (c + 3) & 3);
            CP_COMMIT();
            CP_WAIT(2);
            __syncthreads();
        }

        #pragma unroll
        for (int mt = 0; mt < 4; mt++) {
            #pragma unroll
            for (int rh = 0; rh < 2; rh++) {
                int r = wm * 64 + mt * 16 + gid + rh * 8;
                int aid = said_s[r];
                if (aid < 0) continue;
                float* op = out + (size_t)(aid >> 2) * H + h0 + wn * 32 + tig * 2;
                #pragma unroll
                for (int nt = 0; nt < 4; nt++) {
                    atomicAdd(op + nt * 8,     acc[mt][nt][rh * 2 + 0]);
                    atomicAdd(op + nt * 8 + 1, acc[mt][nt][rh * 2 + 1]);
                }
            }
        }
    }

    // last CTA to finish zeroes g_count for the next graph replay
    __syncthreads();
    if (tid == 0) {
        __threadfence();
        int d = atomicAdd(&g_done, 1);
        if (d == gridDim.x - 1) {
            for (int i = 0; i < E; i++) g_count[i] = 0;
            g_done = 0;
            __threadfence();
        }
    }
}

// ------------------------- launcher ----------------------------------------
extern "C" void kernel_launch(void* const* d_in, const int* in_sizes, int n_in,
                              void* d_out, int out_size) {
    const float* x      = (const float*)d_in[0];
    const float* gate_w = (const float*)d_in[1];
    const float* w_gate = (const float*)d_in[2];
    const float* w_up   = (const float*)d_in[3];
    const float* w_down = (const float*)d_in[4];
    float* out = (float*)d_out;

    cudaFuncSetAttribute(gateup_mma, cudaFuncAttributeMaxDynamicSharedMemorySize, GU_SMEMB);
    cudaFuncSetAttribute(down_mma,   cudaFuncAttributeMaxDynamicSharedMemorySize, DN_SMEMB);

    prep_kernel<<<PREPB, 256>>>(x, gate_w, (const float4*)w_gate,
                                (const float4*)w_up, out);
    gateup_mma<<<296, 256, GU_SMEMB>>>((const float4*)w_down);
    down_mma<<<296, 256, DN_SMEMB>>>(out);
}

// round 16
// speedup vs baseline: 1.0074x; 1.0074x over previous
#include <cuda_runtime.h>
#include <cuda_fp16.h>
#include <math.h>
#include <stdint.h>

#define T 2048
#define H 1024
#define M 512
#define E 32
#define TOPK 4
#define NROWS (T * TOPK)
#define PROWS (NROWS + 128)

// ------------------------- static device scratch ---------------------------
__device__ int      g_count[E];
__device__ int      g_tok[E * T];
__device__ float    g_wt[E * T];
__device__ uint32_t g_hbufw[(size_t)PROWS * M / 2];   // half2 words
__device__ __half   g_xh[(size_t)T * H];
__device__ __half   g_wgh[(size_t)E * M * H];
__device__ __half   g_wuh[(size_t)E * M * H];
__device__ __half   g_wdh[(size_t)E * H * M];

// ------------------------- helpers -----------------------------------------
__device__ __forceinline__ uint32_t smem_u32(const void* p) {
    return (uint32_t)__cvta_generic_to_shared(p);
}
__device__ __forceinline__ uint32_t f2h2(float a, float b) {
    uint32_t r;
    asm("cvt.rn.f16x2.f32 %0, %1, %2;" : "=r"(r) : "f"(b), "f"(a));
    return r;
}
__device__ __forceinline__ uint4 pack4(float4 a, float4 b) {
    uint4 o;
    o.x = f2h2(a.x, a.y); o.y = f2h2(a.z, a.w);
    o.z = f2h2(b.x, b.y); o.w = f2h2(b.z, b.w);
    return o;
}
__device__ __forceinline__ void ldm4(uint32_t* r, uint32_t addr) {
    asm volatile("ldmatrix.sync.aligned.m8n8.x4.shared.b16 {%0,%1,%2,%3}, [%4];"
        : "=r"(r[0]), "=r"(r[1]), "=r"(r[2]), "=r"(r[3]) : "r"(addr));
}
__device__ __forceinline__ void mma_f16(float* c, const uint32_t* a, uint32_t b0, uint32_t b1) {
    asm volatile("mma.sync.aligned.m16n8k16.row.col.f32.f16.f16.f32 "
        "{%0,%1,%2,%3}, {%4,%5,%6,%7}, {%8,%9}, {%0,%1,%2,%3};"
        : "+f"(c[0]), "+f"(c[1]), "+f"(c[2]), "+f"(c[3])
        : "r"(a[0]), "r"(a[1]), "r"(a[2]), "r"(a[3]), "r"(b0), "r"(b1));
}
__device__ __forceinline__ void cp16(uint32_t dst, const void* src, int sz) {
    asm volatile("cp.async.cg.shared.global [%0], [%1], 16, %2;"
        :: "r"(dst), "l"(src), "r"(sz) : "memory");
}
#define CP_COMMIT() asm volatile("cp.async.commit_group;" ::: "memory")
#define CP_WAIT(n)  asm volatile("cp.async.wait_group %0;" :: "n"(n) : "memory")

#define RWORDS 20
#define RBYTES 80
#define NSTAGE 5

// in-block scan of g_count -> soff (row base) and styp (ytile prefix)
#define BLOCK_SCAN(soff, styp)                                             \
    if (wid == 0) {                                                        \
        int c = g_count[lane];                                             \
        int ex = c;                                                        \
        _Pragma("unroll")                                                  \
        for (int o = 1; o < 32; o <<= 1) {                                 \
            int v = __shfl_up_sync(0xffffffffu, ex, o);                    \
            if (lane >= o) ex += v;                                        \
        }                                                                  \
        soff[lane] = ex - c;                                               \
        int ty = (c + 127) >> 7;                                           \
        int tp = ty;                                                       \
        _Pragma("unroll")                                                  \
        for (int o = 1; o < 32; o <<= 1) {                                 \
            int v = __shfl_up_sync(0xffffffffu, tp, o);                    \
            if (lane >= o) tp += v;                                        \
        }                                                                  \
        styp[lane] = tp - ty;                                              \
        if (lane == 31) styp[E] = tp;                                      \
    }                                                                      \
    __syncthreads();

// ------------------------- fused cvt + zero kernel --------------------------
#define NW8  (E * M * H / 8)      // 2097152 per weight tensor
#define NZ4  (T * H / 4)          // 524288 output float4s
#define NTOT (3 * NW8 + NZ4)

__global__ void cvt_all(const float4* __restrict__ wg,
                        const float4* __restrict__ wu,
                        const float4* __restrict__ wd,
                        float* __restrict__ out) {
    int i = blockIdx.x * blockDim.x + threadIdx.x;
    if (i < E) g_count[i] = 0;
    if (i >= NTOT) return;
    if (i < 3 * NW8) {
        const float4* src; uint4* dst; int k;
        if (i < NW8)          { src = wg; dst = (uint4*)g_wgh; k = i; }
        else if (i < 2 * NW8) { src = wu; dst = (uint4*)g_wuh; k = i - NW8; }
        else                  { src = wd; dst = (uint4*)g_wdh; k = i - 2 * NW8; }
        float4 a = src[2 * (size_t)k], b = src[2 * (size_t)k + 1];
        dst[k] = pack4(a, b);
    } else {
        ((float4*)out)[i - 3 * NW8] = make_float4(0.f, 0.f, 0.f, 0.f);
    }
}

// ------------------------- router (+ x fp16 convert) ------------------------
__global__ void router_kernel(const float* __restrict__ x,
                              const float* __restrict__ gate_w) {
    __shared__ float xs[H];
    __shared__ float logits[E];
    int t = blockIdx.x;
    const float* xr = x + (size_t)t * H;
    for (int i = threadIdx.x; i < H; i += blockDim.x) xs[i] = xr[i];
    __syncthreads();
    uint32_t* xh = (uint32_t*)(g_xh + (size_t)t * H);
    for (int i = threadIdx.x; i < H / 2; i += blockDim.x)
        xh[i] = f2h2(xs[2 * i], xs[2 * i + 1]);
    int warp = threadIdx.x >> 5, lane = threadIdx.x & 31;
    for (int e = warp; e < E; e += 4) {
        const float* w = gate_w + (size_t)e * H;
        float s = 0.f;
        for (int i = lane; i < H; i += 32) s += xs[i] * w[i];
        #pragma unroll
        for (int o = 16; o > 0; o >>= 1) s += __shfl_xor_sync(0xffffffffu, s, o);
        if (lane == 0) logits[e] = s;
    }
    __syncthreads();
    if (threadIdx.x == 0) {
        int ids[TOPK]; float vals[TOPK];
        unsigned used = 0;
        for (int k = 0; k < TOPK; k++) {
            float best = -INFINITY; int bi = 0;
            for (int e = 0; e < E; e++)
                if (!((used >> e) & 1u) && logits[e] > best) { best = logits[e]; bi = e; }
            used |= (1u << bi); ids[k] = bi; vals[k] = best;
        }
        float mx = vals[0], se = 0.f, w4[TOPK];
        for (int k = 0; k < TOPK; k++) { w4[k] = expf(vals[k] - mx); se += w4[k]; }
        float inv = 1.0f / se;
        for (int k = 0; k < TOPK; k++) {
            int e = ids[k];
            int pos = atomicAdd(&g_count[e], 1);
            g_tok[e * T + pos] = t * TOPK + k;
            g_wt[e * T + pos] = w4[k] * inv;
        }
    }
}

// ------------------------- gate/up fp16 mma GEMM ---------------------------
// persistent; 256 threads, warps 4x2; block 128 rows x 64 m-cols; K chunk 32
// 5-stage cp.async pipeline (compute; issue(c+4); commit; wait(3); sync)
#define GU_STAGEW 5120
#define GU_STAGEB (GU_STAGEW * 4)          // 20480 bytes
#define GU_SMEMB  (NSTAGE * GU_STAGEB)     // 102400 bytes

__global__ void __launch_bounds__(256, 2)
gateup_mma() {
    extern __shared__ uint32_t sm[];
    __shared__ int   styp[E + 1];
    __shared__ int   soff[E];
    __shared__ int   said_s[128];
    __shared__ float swt_s[128];

    int tid = threadIdx.x, lane = tid & 31, wid = tid >> 5;
    int gid = lane >> 2, tig = lane & 3;
    int wm = wid & 3, wn = wid >> 2;

    BLOCK_SCAN(soff, styp);
    int totalW = styp[E] * 8;

    uint32_t sbase = smem_u32(sm);
    int a_ro = lane & 15;
    int a_kw = (lane >> 4) * 16;
    uint32_t adrA0 = sbase + (uint32_t)(wm * 32 + a_ro) * RBYTES + a_kw;
    uint32_t adrA1 = adrA0 + 16 * RBYTES;
    int b_ro = (lane & 7) + ((lane & 16) >> 1);
    int b_kw = (lane & 8) ? 16 : 0;
    uint32_t adrG0 = sbase + 128 * RBYTES + (uint32_t)(wn * 32 + b_ro) * RBYTES + b_kw;
    uint32_t adrG1 = adrG0 + 16 * RBYTES;
    uint32_t adrU0 = adrG0 + 64 * RBYTES;
    uint32_t adrU1 = adrU0 + 16 * RBYTES;

    int ar = tid >> 1, aj = (tid & 1) * 2;
    int gr = tid >> 2, gj = tid & 3;

    for (int w = blockIdx.x; w < totalW; w += gridDim.x) {
        int ytl = w >> 3, xt = w & 7;
        int e = 0;
        while (styp[e + 1] <= ytl) e++;
        int t0 = (ytl - styp[e]) * 128;
        int m0 = xt * 64;
        int n  = g_count[e];
        int gbase = soff[e] + t0;

        __syncthreads();
        if (tid < 128) {
            int slot = t0 + tid;
            bool v = slot < n;
            said_s[tid] = v ? g_tok[e * T + slot] : -1;
            swt_s[tid]  = v ? g_wt[e * T + slot] : 0.f;
        }
        __syncthreads();

        int aid_a = said_s[ar];
        int apred = (aid_a >= 0) ? 16 : 0;
        const char* asrc0 = (const char*)(g_xh + (size_t)((aid_a < 0 ? 0 : aid_a) >> 2) * H) + aj * 16;
        const char* gsrc0 = (const char*)(g_wgh + ((size_t)e * M + m0 + gr) * H) + gj * 16;
        const char* usrc0 = (const char*)(g_wuh + ((size_t)e * M + m0 + gr) * H) + gj * 16;

        float accG[2][4][4], accU[2][4][4];
        #pragma unroll
        for (int i = 0; i < 2; i++)
            #pragma unroll
            for (int j = 0; j < 4; j++)
                #pragma unroll
                for (int q = 0; q < 4; q++) { accG[i][j][q] = 0.f; accU[i][j][q] = 0.f; }

        auto issue = [&](int c, int s) {
            uint32_t st = sbase + (uint32_t)s * GU_STAGEB;
            const char* as = asrc0 + c * 64;
            cp16(st + ar * RBYTES + aj * 16,      as,      apred);
            cp16(st + ar * RBYTES + aj * 16 + 16, as + 16, apred);
            cp16(st + 128 * RBYTES + gr * RBYTES + gj * 16, gsrc0 + c * 64, 16);
            cp16(st + 192 * RBYTES + gr * RBYTES + gj * 16, usrc0 + c * 64, 16);
        };
        auto compute = [&](int s) {
            uint32_t so = (uint32_t)s * GU_STAGEB;
            #pragma unroll
            for (int sub = 0; sub < 2; sub++) {
                uint32_t soo = so + sub * 32;
                uint32_t a0[4], a1[4], g0[4], g1[4], u0[4], u1[4];
                ldm4(a0, adrA0 + soo); ldm4(a1, adrA1 + soo);
                ldm4(g0, adrG0 + soo); ldm4(g1, adrG1 + soo);
                ldm4(u0, adrU0 + soo); ldm4(u1, adrU1 + soo);
                #pragma unroll
                for (int p = 0; p < 2; p++) {
                    const uint32_t* gg = p ? g1 : g0;
                    const uint32_t* uu = p ? u1 : u0;
                    #pragma unroll
                    for (int q = 0; q < 2; q++) {
                        int nt = p * 2 + q;
                        mma_f16(accG[0][nt], a0, gg[q * 2], gg[q * 2 + 1]);
                        mma_f16(accG[1][nt], a1, gg[q * 2], gg[q * 2 + 1]);
                        mma_f16(accU[0][nt], a0, uu[q * 2], uu[q * 2 + 1]);
                        mma_f16(accU[1][nt], a1, uu[q * 2], uu[q * 2 + 1]);
                    }
                }
            }
        };

        const int NC = H / 32;   // 32
        issue(0, 0); CP_COMMIT();
        issue(1, 1); CP_COMMIT();
        issue(2, 2); CP_COMMIT();
        issue(3, 3); CP_COMMIT();
        CP_WAIT(3);
        __syncthreads();
        int st = 0;
        for (int c = 0; c < NC; c++) {
            compute(st);
            if (c + 4 < NC) {
                int s4 = st + 4 - ((st + 4 >= NSTAGE) ? NSTAGE : 0);
                issue(c + 4, s4);
            }
            CP_COMMIT();
            CP_WAIT(3);
            __syncthreads();
            if (++st == NSTAGE) st = 0;
        }

        // epilogue: h = silu(gate)*up*route_w -> half2 words
        #pragma unroll
        for (int mt = 0; mt < 2; mt++) {
            #pragma unroll
            for (int rh = 0; rh < 2; rh++) {
                int r = wm * 32 + mt * 16 + gid + rh * 8;
                int said = said_s[r];
                if (said < 0) continue;
                float wv = swt_s[r];
                uint32_t* hp = g_hbufw + (size_t)(gbase + r) * (M / 2)
                             + ((m0 + wn * 32) >> 1) + tig;
                #pragma unroll
                for (int nt = 0; nt < 4; nt++) {
                    float g0 = accG[mt][nt][rh * 2 + 0];
                    float g1 = accG[mt][nt][rh * 2 + 1];
                    float u0 = accU[mt][nt][rh * 2 + 0];
                    float u1 = accU[mt][nt][rh * 2 + 1];
                    float o0 = (g0 / (1.f + __expf(-g0))) * u0 * wv;
                    float o1 = (g1 / (1.f + __expf(-g1))) * u1 * wv;
                    hp[nt * 4] = f2h2(o0, o1);
                }
            }
        }
    }
}

// ------------------------- down fp16 mma GEMM ------------------------------
#define DN_STAGEW 5120
#define DN_STAGEB (DN_STAGEW * 4)
#define DN_SMEMB  (NSTAGE * DN_STAGEB)     // 102400 bytes

__global__ void __launch_bounds__(256, 2)
down_mma(float* __restrict__ out) {
    extern __shared__ uint32_t sm[];
    __shared__ int styp[E + 1];
    __shared__ int soff[E];
    __shared__ int said_s[128];

    int tid = threadIdx.x, lane = tid & 31, wid = tid >> 5;
    int gid = lane >> 2, tig = lane & 3;
    int wm = wid & 1, wn = wid >> 1;

    BLOCK_SCAN(soff, styp);
    int totalW = styp[E] * 8;

    uint32_t sbase = smem_u32(sm);
    int a_ro = lane & 15;
    int a_kw = (lane >> 4) * 16;
    uint32_t adrA[4];
    #pragma unroll
    for (int mt = 0; mt < 4; mt++)
        adrA[mt] = sbase + (uint32_t)(wm * 64 + mt * 16 + a_ro) * RBYTES + a_kw;
    int b_ro = (lane & 7) + ((lane & 16) >> 1);
    int b_kw = (lane & 8) ? 16 : 0;
    uint32_t adrW0 = sbase + 128 * RBYTES + (uint32_t)(wn * 32 + b_ro) * RBYTES + b_kw;
    uint32_t adrW1 = adrW0 + 16 * RBYTES;

    int ar = tid >> 1, aj = (tid & 1) * 2;

    for (int w = blockIdx.x; w < totalW; w += gridDim.x) {
        int ytl = w >> 3, xt = w & 7;
        int e = 0;
        while (styp[e + 1] <= ytl) e++;
        int t0 = (ytl - styp[e]) * 128;
        int h0 = xt * 128;
        int n  = g_count[e];
        int gbase = soff[e] + t0;

        __syncthreads();
        if (tid < 128) {
            int slot = t0 + tid;
            said_s[tid] = (slot < n) ? g_tok[e * T + slot] : -1;
        }
        __syncthreads();

        const char* asrc0 = (const char*)(g_hbufw + (size_t)(gbase + ar) * (M / 2)) + aj * 16;
        const char* wsrc0 = (const char*)(g_wdh + ((size_t)e * H + h0 + ar) * M) + aj * 16;

        float acc[4][4][4];
        #pragma unroll
        for (int i = 0; i < 4; i++)
            #pragma unroll
            for (int j = 0; j < 4; j++)
                #pragma unroll
                for (int q = 0; q < 4; q++) acc[i][j][q] = 0.f;

        auto issue = [&](int c, int s) {
            uint32_t st = sbase + (uint32_t)s * DN_STAGEB;
            const char* as = asrc0 + c * 64;
            const char* ws = wsrc0 + c * 64;
            cp16(st + ar * RBYTES + aj * 16,      as,      16);
            cp16(st + ar * RBYTES + aj * 16 + 16, as + 16, 16);
            cp16(st + 128 * RBYTES + ar * RBYTES + aj * 16,      ws,      16);
            cp16(st + 128 * RBYTES + ar * RBYTES + aj * 16 + 16, ws + 16, 16);
        };
        auto compute = [&](int s) {
            uint32_t so = (uint32_t)s * DN_STAGEB;
            #pragma unroll
            for (int sub = 0; sub < 2; sub++) {
                uint32_t soo = so + sub * 32;
                uint32_t a[4][4], w0[4], w1[4];
                #pragma unroll
                for (int mt = 0; mt < 4; mt++) ldm4(a[mt], adrA[mt] + soo);
                ldm4(w0, adrW0 + soo); ldm4(w1, adrW1 + soo);
                #pragma unroll
                for (int p = 0; p < 2; p++) {
                    const uint32_t* ww = p ? w1 : w0;
                    #pragma unroll
                    for (int q = 0; q < 2; q++) {
                        int nt = p * 2 + q;
                        #pragma unroll
                        for (int mt = 0; mt < 4; mt++)
                            mma_f16(acc[mt][nt], a[mt], ww[q * 2], ww[q * 2 + 1]);
                    }
                }
            }
        };

        const int NC = M / 32;   // 16
        issue(0, 0); CP_COMMIT();
        issue(1, 1); CP_COMMIT();
        issue(2, 2); CP_COMMIT();
        issue(3, 3); CP_COMMIT();
        CP_WAIT(3);
        __syncthreads();
        int st = 0;
        for (int c = 0; c < NC; c++) {
            compute(st);
            if (c + 4 < NC) {
                int s4 = st + 4 - ((st + 4 >= NSTAGE) ? NSTAGE : 0);
                issue(c + 4, s4);
            }
            CP_COMMIT();
            CP_WAIT(3);
            __syncthreads();
            if (++st == NSTAGE) st = 0;
        }

        #pragma unroll
        for (int mt = 0; mt < 4; mt++) {
            #pragma unroll
            for (int rh = 0; rh < 2; rh++) {
                int r = wm * 64 + mt * 16 + gid + rh * 8;
                int aid = said_s[r];
                if (aid < 0) continue;
                float* op = out + (size_t)(aid >> 2) * H + h0 + wn * 32 + tig * 2;
                #pragma unroll
                for (int nt = 0; nt < 4; nt++) {
                    atomicAdd(op + nt * 8,     acc[mt][nt][rh * 2 + 0]);
                    atomicAdd(op + nt * 8 + 1, acc[mt][nt][rh * 2 + 1]);
                }
            }
        }
    }
}

// ------------------------- launcher ----------------------------------------
extern "C" void kernel_launch(void* const* d_in, const int* in_sizes, int n_in,
                              void* d_out, int out_size) {
    const float* x      = (const float*)d_in[0];
    const float* gate_w = (const float*)d_in[1];
    const float* w_gate = (const float*)d_in[2];
    const float* w_up   = (const float*)d_in[3];
    const float* w_down = (const float*)d_in[4];
    float* out = (float*)d_out;

    cudaFuncSetAttribute(gateup_mma, cudaFuncAttributeMaxDynamicSharedMemorySize, GU_SMEMB);
    cudaFuncSetAttribute(down_mma,   cudaFuncAttributeMaxDynamicSharedMemorySize, DN_SMEMB);

    cvt_all<<<(NTOT + 255) / 256, 256>>>((const float4*)w_gate, (const float4*)w_up,
                                         (const float4*)w_down, out);
    router_kernel<<<T, 128>>>(x, gate_w);
    gateup_mma<<<296, 256, GU_SMEMB>>>();
    down_mma<<<296, 256, DN_SMEMB>>>(out);
}

// round 17
// speedup vs baseline: 1.0875x; 1.0795x over previous
#include <cuda_runtime.h>
#include <cuda_fp16.h>
#include <math.h>
#include <stdint.h>

#define T 2048
#define H 1024
#define M 512
#define E 32
#define TOPK 4
#define NROWS (T * TOPK)
#define PROWS (NROWS + 128)
#define MAXTILES 768

// ------------------------- static device scratch ---------------------------
__device__ int      g_count[E];
__device__ int      g_tok[E * T];
__device__ float    g_wt[E * T];
__device__ uint32_t g_hbufw[(size_t)PROWS * M / 2];   // half2 words
__device__ __half   g_xh[(size_t)T * H];
__device__ __half   g_wgh[(size_t)E * M * H];
__device__ __half   g_wuh[(size_t)E * M * H];
__device__ __half   g_wdh[(size_t)E * H * M];

// ------------------------- helpers -----------------------------------------
__device__ __forceinline__ uint32_t smem_u32(const void* p) {
    return (uint32_t)__cvta_generic_to_shared(p);
}
__device__ __forceinline__ uint32_t f2h2(float a, float b) {
    uint32_t r;
    asm("cvt.rn.f16x2.f32 %0, %1, %2;" : "=r"(r) : "f"(b), "f"(a));
    return r;
}
__device__ __forceinline__ uint4 pack4(float4 a, float4 b) {
    uint4 o;
    o.x = f2h2(a.x, a.y); o.y = f2h2(a.z, a.w);
    o.z = f2h2(b.x, b.y); o.w = f2h2(b.z, b.w);
    return o;
}
__device__ __forceinline__ void ldm4(uint32_t* r, uint32_t addr) {
    asm volatile("ldmatrix.sync.aligned.m8n8.x4.shared.b16 {%0,%1,%2,%3}, [%4];"
        : "=r"(r[0]), "=r"(r[1]), "=r"(r[2]), "=r"(r[3]) : "r"(addr));
}
__device__ __forceinline__ void mma_f16(float* c, const uint32_t* a, uint32_t b0, uint32_t b1) {
    asm volatile("mma.sync.aligned.m16n8k16.row.col.f32.f16.f16.f32 "
        "{%0,%1,%2,%3}, {%4,%5,%6,%7}, {%8,%9}, {%0,%1,%2,%3};"
        : "+f"(c[0]), "+f"(c[1]), "+f"(c[2]), "+f"(c[3])
        : "r"(a[0]), "r"(a[1]), "r"(a[2]), "r"(a[3]), "r"(b0), "r"(b1));
}
__device__ __forceinline__ void cp16(uint32_t dst, const void* src, int sz) {
    asm volatile("cp.async.cg.shared.global [%0], [%1], 16, %2;"
        :: "r"(dst), "l"(src), "r"(sz) : "memory");
}
#define CP_COMMIT() asm volatile("cp.async.commit_group;" ::: "memory")
#define CP_WAIT(n)  asm volatile("cp.async.wait_group %0;" :: "n"(n) : "memory")

#define RWORDS 20
#define RBYTES 80

// in-block scan of g_count -> soff (row base) and styp (ytile prefix)
#define BLOCK_SCAN(soff, styp)                                             \
    if (wid == 0) {                                                        \
        int c = g_count[lane];                                             \
        int ex = c;                                                        \
        _Pragma("unroll")                                                  \
        for (int o = 1; o < 32; o <<= 1) {                                 \
            int v = __shfl_up_sync(0xffffffffu, ex, o);                    \
            if (lane >= o) ex += v;                                        \
        }                                                                  \
        soff[lane] = ex - c;                                               \
        int ty = (c + 127) >> 7;                                           \
        int tp = ty;                                                       \
        _Pragma("unroll")                                                  \
        for (int o = 1; o < 32; o <<= 1) {                                 \
            int v = __shfl_up_sync(0xffffffffu, tp, o);                    \
            if (lane >= o) tp += v;                                        \
        }                                                                  \
        styp[lane] = tp - ty;                                              \
        if (lane == 31) styp[E] = tp;                                      \
    }                                                                      \
    __syncthreads();

// ------------------------- fused cvt + zero kernel --------------------------
#define NW8  (E * M * H / 8)
#define NZ4  (T * H / 4)
#define NTOT (3 * NW8 + NZ4)

__global__ void cvt_all(const float4* __restrict__ wg,
                        const float4* __restrict__ wu,
                        const float4* __restrict__ wd,
                        float* __restrict__ out) {
    int i = blockIdx.x * blockDim.x + threadIdx.x;
    if (i < E) g_count[i] = 0;
    if (i >= NTOT) return;
    if (i < 3 * NW8) {
        const float4* src; uint4* dst; int k;
        if (i < NW8)          { src = wg; dst = (uint4*)g_wgh; k = i; }
        else if (i < 2 * NW8) { src = wu; dst = (uint4*)g_wuh; k = i - NW8; }
        else                  { src = wd; dst = (uint4*)g_wdh; k = i - 2 * NW8; }
        float4 a = src[2 * (size_t)k], b = src[2 * (size_t)k + 1];
        dst[k] = pack4(a, b);
    } else {
        ((float4*)out)[i - 3 * NW8] = make_float4(0.f, 0.f, 0.f, 0.f);
    }
}

// ------------------------- router (+ x fp16 convert) ------------------------
__global__ void router_kernel(const float* __restrict__ x,
                              const float* __restrict__ gate_w) {
    __shared__ float xs[H];
    __shared__ float logits[E];
    int t = blockIdx.x;
    const float* xr = x + (size_t)t * H;
    for (int i = threadIdx.x; i < H; i += blockDim.x) xs[i] = xr[i];
    __syncthreads();
    uint32_t* xh = (uint32_t*)(g_xh + (size_t)t * H);
    for (int i = threadIdx.x; i < H / 2; i += blockDim.x)
        xh[i] = f2h2(xs[2 * i], xs[2 * i + 1]);
    int warp = threadIdx.x >> 5, lane = threadIdx.x & 31;
    for (int e = warp; e < E; e += 4) {
        const float* w = gate_w + (size_t)e * H;
        float s = 0.f;
        for (int i = lane; i < H; i += 32) s += xs[i] * w[i];
        #pragma unroll
        for (int o = 16; o > 0; o >>= 1) s += __shfl_xor_sync(0xffffffffu, s, o);
        if (lane == 0) logits[e] = s;
    }
    __syncthreads();
    if (threadIdx.x == 0) {
        int ids[TOPK]; float vals[TOPK];
        unsigned used = 0;
        for (int k = 0; k < TOPK; k++) {
            float best = -INFINITY; int bi = 0;
            for (int e = 0; e < E; e++)
                if (!((used >> e) & 1u) && logits[e] > best) { best = logits[e]; bi = e; }
            used |= (1u << bi); ids[k] = bi; vals[k] = best;
        }
        float mx = vals[0], se = 0.f, w4[TOPK];
        for (int k = 0; k < TOPK; k++) { w4[k] = expf(vals[k] - mx); se += w4[k]; }
        float inv = 1.0f / se;
        for (int k = 0; k < TOPK; k++) {
            int e = ids[k];
            int pos = atomicAdd(&g_count[e], 1);
            g_tok[e * T + pos] = t * TOPK + k;
            g_wt[e * T + pos] = w4[k] * inv;
        }
    }
}

// ------------------------- gate/up fp16 mma GEMM ---------------------------
// ONE TILE PER BLOCK (non-persistent, hardware backfill); grid = MAXTILES
// 256 threads, warps 4x2; block 128 rows x 64 m-cols; 4-stage cp.async
#define GU_STAGEW 5120
#define GU_STAGEB (GU_STAGEW * 4)
#define GU_SMEMB  (4 * GU_STAGEB)          // 81920 bytes

__global__ void __launch_bounds__(256, 2)
gateup_mma() {
    extern __shared__ uint32_t sm[];
    __shared__ int   styp[E + 1];
    __shared__ int   soff[E];
    __shared__ int   said_s[128];
    __shared__ float swt_s[128];

    int tid = threadIdx.x, lane = tid & 31, wid = tid >> 5;
    int gid = lane >> 2, tig = lane & 3;
    int wm = wid & 3, wn = wid >> 2;

    BLOCK_SCAN(soff, styp);
    int totalW = styp[E] * 8;
    int w = blockIdx.x;
    if (w >= totalW) return;

    uint32_t sbase = smem_u32(sm);
    int a_ro = lane & 15;
    int a_kw = (lane >> 4) * 16;
    uint32_t adrA0 = sbase + (uint32_t)(wm * 32 + a_ro) * RBYTES + a_kw;
    uint32_t adrA1 = adrA0 + 16 * RBYTES;
    int b_ro = (lane & 7) + ((lane & 16) >> 1);
    int b_kw = (lane & 8) ? 16 : 0;
    uint32_t adrG0 = sbase + 128 * RBYTES + (uint32_t)(wn * 32 + b_ro) * RBYTES + b_kw;
    uint32_t adrG1 = adrG0 + 16 * RBYTES;
    uint32_t adrU0 = adrG0 + 64 * RBYTES;
    uint32_t adrU1 = adrU0 + 16 * RBYTES;

    int ar = tid >> 1, aj = (tid & 1) * 2;
    int gr = tid >> 2, gj = tid & 3;

    int ytl = w >> 3, xt = w & 7;
    int e = 0;
    while (styp[e + 1] <= ytl) e++;
    int t0 = (ytl - styp[e]) * 128;
    int m0 = xt * 64;
    int n  = g_count[e];
    int gbase = soff[e] + t0;

    if (tid < 128) {
        int slot = t0 + tid;
        bool v = slot < n;
        said_s[tid] = v ? g_tok[e * T + slot] : -1;
        swt_s[tid]  = v ? g_wt[e * T + slot] : 0.f;
    }
    __syncthreads();

    int aid_a = said_s[ar];
    int apred = (aid_a >= 0) ? 16 : 0;
    const char* asrc0 = (const char*)(g_xh + (size_t)((aid_a < 0 ? 0 : aid_a) >> 2) * H) + aj * 16;
    const char* gsrc0 = (const char*)(g_wgh + ((size_t)e * M + m0 + gr) * H) + gj * 16;
    const char* usrc0 = (const char*)(g_wuh + ((size_t)e * M + m0 + gr) * H) + gj * 16;

    float accG[2][4][4], accU[2][4][4];
    #pragma unroll
    for (int i = 0; i < 2; i++)
        #pragma unroll
        for (int j = 0; j < 4; j++)
            #pragma unroll
            for (int q = 0; q < 4; q++) { accG[i][j][q] = 0.f; accU[i][j][q] = 0.f; }

    auto issue = [&](int c, int s) {
        uint32_t st = sbase + (uint32_t)s * GU_STAGEB;
        const char* as = asrc0 + c * 64;
        cp16(st + ar * RBYTES + aj * 16,      as,      apred);
        cp16(st + ar * RBYTES + aj * 16 + 16, as + 16, apred);
        cp16(st + 128 * RBYTES + gr * RBYTES + gj * 16, gsrc0 + c * 64, 16);
        cp16(st + 192 * RBYTES + gr * RBYTES + gj * 16, usrc0 + c * 64, 16);
    };
    auto compute = [&](int s) {
        uint32_t so = (uint32_t)s * GU_STAGEB;
        #pragma unroll
        for (int sub = 0; sub < 2; sub++) {
            uint32_t soo = so + sub * 32;
            uint32_t a0[4], a1[4], g0[4], g1[4], u0[4], u1[4];
            ldm4(a0, adrA0 + soo); ldm4(a1, adrA1 + soo);
            ldm4(g0, adrG0 + soo); ldm4(g1, adrG1 + soo);
            ldm4(u0, adrU0 + soo); ldm4(u1, adrU1 + soo);
            #pragma unroll
            for (int p = 0; p < 2; p++) {
                const uint32_t* gg = p ? g1 : g0;
                const uint32_t* uu = p ? u1 : u0;
                #pragma unroll
                for (int q = 0; q < 2; q++) {
                    int nt = p * 2 + q;
                    mma_f16(accG[0][nt], a0, gg[q * 2], gg[q * 2 + 1]);
                    mma_f16(accG[1][nt], a1, gg[q * 2], gg[q * 2 + 1]);
                    mma_f16(accU[0][nt], a0, uu[q * 2], uu[q * 2 + 1]);
                    mma_f16(accU[1][nt], a1, uu[q * 2], uu[q * 2 + 1]);
                }
            }
        }
    };

    const int NC = H / 32;   // 32
    issue(0, 0); CP_COMMIT();
    issue(1, 1); CP_COMMIT();
    issue(2, 2); CP_COMMIT();
    CP_WAIT(2);
    __syncthreads();
    for (int c = 0; c < NC; c++) {
        compute(c & 3);
        if (c + 3 < NC) issue(c + 3, (c + 3) & 3);
        CP_COMMIT();
        CP_WAIT(2);
        __syncthreads();
    }

    // epilogue: h = silu(gate)*up*route_w -> half2 words
    #pragma unroll
    for (int mt = 0; mt < 2; mt++) {
        #pragma unroll
        for (int rh = 0; rh < 2; rh++) {
            int r = wm * 32 + mt * 16 + gid + rh * 8;
            int said = said_s[r];
            if (said < 0) continue;
            float wv = swt_s[r];
            uint32_t* hp = g_hbufw + (size_t)(gbase + r) * (M / 2)
                         + ((m0 + wn * 32) >> 1) + tig;
            #pragma unroll
            for (int nt = 0; nt < 4; nt++) {
                float g0 = accG[mt][nt][rh * 2 + 0];
                float g1 = accG[mt][nt][rh * 2 + 1];
                float u0 = accU[mt][nt][rh * 2 + 0];
                float u1 = accU[mt][nt][rh * 2 + 1];
                float o0 = (g0 / (1.f + __expf(-g0))) * u0 * wv;
                float o1 = (g1 / (1.f + __expf(-g1))) * u1 * wv;
                hp[nt * 4] = f2h2(o0, o1);
            }
        }
    }
}

// ------------------------- down fp16 mma GEMM ------------------------------
// ONE TILE PER BLOCK; grid = MAXTILES; 256 threads, warps 2x4; block 128x128
#define DN_STAGEW 5120
#define DN_STAGEB (DN_STAGEW * 4)
#define DN_SMEMB  (4 * DN_STAGEB)          // 81920 bytes

__global__ void __launch_bounds__(256, 2)
down_mma(float* __restrict__ out) {
    extern __shared__ uint32_t sm[];
    __shared__ int styp[E + 1];
    __shared__ int soff[E];
    __shared__ int said_s[128];

    int tid = threadIdx.x, lane = tid & 31, wid = tid >> 5;
    int gid = lane >> 2, tig = lane & 3;
    int wm = wid & 1, wn = wid >> 1;

    BLOCK_SCAN(soff, styp);
    int totalW = styp[E] * 8;
    int w = blockIdx.x;
    if (w >= totalW) return;

    uint32_t sbase = smem_u32(sm);
    int a_ro = lane & 15;
    int a_kw = (lane >> 4) * 16;
    uint32_t adrA[4];
    #pragma unroll
    for (int mt = 0; mt < 4; mt++)
        adrA[mt] = sbase + (uint32_t)(wm * 64 + mt * 16 + a_ro) * RBYTES + a_kw;
    int b_ro = (lane & 7) + ((lane & 16) >> 1);
    int b_kw = (lane & 8) ? 16 : 0;
    uint32_t adrW0 = sbase + 128 * RBYTES + (uint32_t)(wn * 32 + b_ro) * RBYTES + b_kw;
    uint32_t adrW1 = adrW0 + 16 * RBYTES;

    int ar = tid >> 1, aj = (tid & 1) * 2;

    int ytl = w >> 3, xt = w & 7;
    int e = 0;
    while (styp[e + 1] <= ytl) e++;
    int t0 = (ytl - styp[e]) * 128;
    int h0 = xt * 128;
    int n  = g_count[e];
    int gbase = soff[e] + t0;

    if (tid < 128) {
        int slot = t0 + tid;
        said_s[tid] = (slot < n) ? g_tok[e * T + slot] : -1;
    }
    __syncthreads();

    const char* asrc0 = (const char*)(g_hbufw + (size_t)(gbase + ar) * (M / 2)) + aj * 16;
    const char* wsrc0 = (const char*)(g_wdh + ((size_t)e * H + h0 + ar) * M) + aj * 16;

    float acc[4][4][4];
    #pragma unroll
    for (int i = 0; i < 4; i++)
        #pragma unroll
        for (int j = 0; j < 4; j++)
            #pragma unroll
            for (int q = 0; q < 4; q++) acc[i][j][q] = 0.f;

    auto issue = [&](int c, int s) {
        uint32_t st = sbase + (uint32_t)s * DN_STAGEB;
        const char* as = asrc0 + c * 64;
        const char* ws = wsrc0 + c * 64;
        cp16(st + ar * RBYTES + aj * 16,      as,      16);
        cp16(st + ar * RBYTES + aj * 16 + 16, as + 16, 16);
        cp16(st + 128 * RBYTES + ar * RBYTES + aj * 16,      ws,      16);
        cp16(st + 128 * RBYTES + ar * RBYTES + aj * 16 + 16, ws + 16, 16);
    };
    auto compute = [&](int s) {
        uint32_t so = (uint32_t)s * DN_STAGEB;
        #pragma unroll
        for (int sub = 0; sub < 2; sub++) {
            uint32_t soo = so + sub * 32;
            uint32_t a[4][4], w0[4], w1[4];
            #pragma unroll
            for (int mt = 0; mt < 4; mt++) ldm4(a[mt], adrA[mt] + soo);
            ldm4(w0, adrW0 + soo); ldm4(w1, adrW1 + soo);
            #pragma unroll
            for (int p = 0; p < 2; p++) {
                const uint32_t* ww = p ? w1 : w0;
                #pragma unroll
                for (int q = 0; q < 2; q++) {
                    int nt = p * 2 + q;
                    #pragma unroll
                    for (int mt = 0; mt < 4; mt++)
                        mma_f16(acc[mt][nt], a[mt], ww[q * 2], ww[q * 2 + 1]);
                }
            }
        }
    };

    const int NC = M / 32;   // 16
    issue(0, 0); CP_COMMIT();
    issue(1, 1); CP_COMMIT();
    issue(2, 2); CP_COMMIT();
    CP_WAIT(2);
    __syncthreads();
    for (int c = 0; c < NC; c++) {
        compute(c & 3);
        if (c + 3 < NC) issue(c + 3, (c + 3) & 3);
        CP_COMMIT();
        CP_WAIT(2);
        __syncthreads();
    }

    #pragma unroll
    for (int mt = 0; mt < 4; mt++) {
        #pragma unroll
        for (int rh = 0; rh < 2; rh++) {
            int r = wm * 64 + mt * 16 + gid + rh * 8;
            int aid = said_s[r];
            if (aid < 0) continue;
            float* op = out + (size_t)(aid >> 2) * H + h0 + wn * 32 + tig * 2;
            #pragma unroll
            for (int nt = 0; nt < 4; nt++) {
                atomicAdd(op + nt * 8,     acc[mt][nt][rh * 2 + 0]);
                atomicAdd(op + nt * 8 + 1, acc[mt][nt][rh * 2 + 1]);
            }
        }
    }
}

// ------------------------- launcher ----------------------------------------
extern "C" void kernel_launch(void* const* d_in, const int* in_sizes, int n_in,
                              void* d_out, int out_size) {
    const float* x      = (const float*)d_in[0];
    const float* gate_w = (const float*)d_in[1];
    const float* w_gate = (const float*)d_in[2];
    const float* w_up   = (const float*)d_in[3];
    const float* w_down = (const float*)d_in[4];
    float* out = (float*)d_out;

    cudaFuncSetAttribute(gateup_mma, cudaFuncAttributeMaxDynamicSharedMemorySize, GU_SMEMB);
    cudaFuncSetAttribute(down_mma,   cudaFuncAttributeMaxDynamicSharedMemorySize, DN_SMEMB);

    cvt_all<<<(NTOT + 255) / 256, 256>>>((const float4*)w_gate, (const float4*)w_up,
                                         (const float4*)w_down, out);
    router_kernel<<<T, 128>>>(x, gate_w);
    gateup_mma<<<MAXTILES, 256, GU_SMEMB>>>();
    down_mma<<<MAXTILES, 256, DN_SMEMB>>>(out);
}